// round 16
// baseline (speedup 1.0000x reference)
#include <cuda_runtime.h>

// PatchShuffle: RATIO=0.75, NUM_ROWS=16, NUM_COLS=64, T=1024, B=64, C=768, STRIPE_W=48
// Output layout (flat fp32):
//   visible [12,582,912] | fwd [65,536] | bwd [65,536] | stripe_bounds [128]
//
// R10 structure with 256-bit vector memory ops (sm_100+ LDG.256/STG.256):
// 3 x 32B loads + 3 x 32B evict-first stores per thread instead of 6+6 x 16B.
// Halves LSU/L1tex/L2 transaction counts at identical byte traffic.

#define NCOLS    64
#define BATCH    64
#define SW       48
#define NVIS     16
#define ROW_F8   96            // 32-byte chunks per (t,b) row (3072 B / 32)
#define VIS_ELEMS 12582912LL
#define NBLOCKS  2048u         // 16384 rows / 8 warps per block

__device__ __forceinline__ int perm_of(int j, int s) {
    return (j < NVIS) ? ((j < s) ? j : j + SW) : (s + (j - NVIS));
}

struct __align__(32) f8 { float v[8]; };

__device__ __forceinline__ f8 ldg256(const f8* p) {
    f8 r;
    asm volatile("ld.global.nc.v8.f32 {%0,%1,%2,%3,%4,%5,%6,%7}, [%8];"
                 : "=f"(r.v[0]), "=f"(r.v[1]), "=f"(r.v[2]), "=f"(r.v[3]),
                   "=f"(r.v[4]), "=f"(r.v[5]), "=f"(r.v[6]), "=f"(r.v[7])
                 : "l"(p));
    return r;
}

__device__ __forceinline__ void stg256_cs(f8* p, const f8& r) {
    asm volatile("st.global.cs.v8.f32 [%0], {%1,%2,%3,%4,%5,%6,%7,%8};"
                 :: "l"(p),
                    "f"(r.v[0]), "f"(r.v[1]), "f"(r.v[2]), "f"(r.v[3]),
                    "f"(r.v[4]), "f"(r.v[5]), "f"(r.v[6]), "f"(r.v[7])
                 : "memory");
}

__global__ void __launch_bounds__(256)
patch_shuffle_fused(const f8* __restrict__ patches,
                    const int* __restrict__ start_cols,
                    float*     __restrict__ out) {
    const unsigned tid = threadIdx.x;
    const unsigned blk = blockIdx.x;

    // ---- index outputs folded into gather blocks: 64 elems per block ----
    if (tid < 64) {
        unsigned k = blk * 64 + tid;           // covers [0, 131072) exactly
        if (k < 65536) {
            // fwd[t, b]
            int b = k & 63;
            int t = k >> 6;
            int j = t & 63, r = t >> 6;
            int s = __ldg(&start_cols[b]);
            __stcs(&out[VIS_ELEMS + k], (float)(r * NCOLS + perm_of(j, s)));
        } else {
            // bwd[p, b] (closed-form inverse)
            unsigned m = k - 65536;
            int b = m & 63;
            int p = m >> 6;
            int c = p & 63, r = p >> 6;
            int s = __ldg(&start_cols[b]);
            int inv = (c < s) ? c : ((c < s + SW) ? (NVIS + c - s) : (c - SW));
            __stcs(&out[VIS_ELEMS + 65536 + m], (float)(r * NCOLS + inv));
        }
    } else if (blk == 0 && tid < 192) {
        // stripe_bounds: 128 elems, row 0 = start, row 1 = start + SW
        unsigned m = tid - 64;
        int b = m & 63;
        int s = __ldg(&start_cols[b]);
        __stcs(&out[VIS_ELEMS + 131072 + m], (float)((m < 64) ? s : s + SW));
    }

    // ---- gather: one warp per output row; 3 front-batched LDG.256 ----
    unsigned warp = blk * 8 + (tid >> 5);
    int lane = tid & 31;
    int b = warp & 63;
    int t = warp >> 6;                         // t in [0,256)
    int j = t & 63;
    int r = t >> 6;
    int s = __ldg(&start_cols[b]);
    int src_t = r * NCOLS + perm_of(j, s);

    const f8* src = patches + ((long)src_t * BATCH + b) * ROW_F8 + lane;
    f8*       dst = (f8*)out + (long)warp * ROW_F8 + lane;

    f8 v0 = ldg256(src + 0);
    f8 v1 = ldg256(src + 32);
    f8 v2 = ldg256(src + 64);
    // streaming 256-bit stores: evict-first keeps input L2-resident across replays
    stg256_cs(dst + 0,  v0);
    stg256_cs(dst + 32, v1);
    stg256_cs(dst + 64, v2);
}

extern "C" void kernel_launch(void* const* d_in, const int* in_sizes, int n_in,
                              void* d_out, int out_size) {
    const f8*  patches    = (const f8*)d_in[0];
    const int* start_cols = (const int*)d_in[1];
    float*     out        = (float*)d_out;

    patch_shuffle_fused<<<NBLOCKS, 256>>>(patches, start_cols, out);
}

// round 17
// speedup vs baseline: 1.1830x; 1.1830x over previous
#include <cuda_runtime.h>

// PatchShuffle: RATIO=0.75, NUM_ROWS=16, NUM_COLS=64, T=1024, B=64, C=768, STRIPE_W=48
// Output layout (flat fp32):
//   visible [12,582,912] | fwd [65,536] | bwd [65,536] | stripe_bounds [128]
//
// FINAL — converged at the write-bandwidth roofline (median 12.9 us over 5
// measurements; 1.5x vs first correct kernel). Configuration:
//  - single launch; index outputs folded into the gather blocks
//  - one warp per output row; 6 front-batched LDG.128 (true MLP=6 at 32 regs)
//  - closed-form permutation (no argsort): perm/inverse computed inline
//  - default-policy reads: the 50 MB input stays L2-resident across graph replays
//  - __stcs evict-first stores: write-combined streaming drain, no input eviction
// Floor = mandatory 50.6 MB output write stream to DRAM (~3.9 TB/s drain).
// Tested-equivalent (noise): 1184-block single wave, 2-rows-per-warp MLP-12.
// Tested-regressions: __stwt, evict_last reads, cp.async.bulk engines, LDG.256.

#define NCOLS    64
#define BATCH    64
#define SW       48
#define NVIS     16
#define ROW_F4   192           // float4 per (t,b) row
#define VIS_ELEMS 12582912LL
#define NBLOCKS  2048u         // 16384 rows / 8 warps per block

__device__ __forceinline__ int perm_of(int j, int s) {
    return (j < NVIS) ? ((j < s) ? j : j + SW) : (s + (j - NVIS));
}

__global__ void __launch_bounds__(256)
patch_shuffle_fused(const float4* __restrict__ patches,
                    const int*    __restrict__ start_cols,
                    float*        __restrict__ out) {
    const unsigned tid = threadIdx.x;
    const unsigned blk = blockIdx.x;

    // ---- index outputs folded into gather blocks: 64 elems per block ----
    if (tid < 64) {
        unsigned k = blk * 64 + tid;           // covers [0, 131072) exactly
        if (k < 65536) {
            // fwd[t, b]
            int b = k & 63;
            int t = k >> 6;
            int j = t & 63, r = t >> 6;
            int s = __ldg(&start_cols[b]);
            __stcs(&out[VIS_ELEMS + k], (float)(r * NCOLS + perm_of(j, s)));
        } else {
            // bwd[p, b] (closed-form inverse)
            unsigned m = k - 65536;
            int b = m & 63;
            int p = m >> 6;
            int c = p & 63, r = p >> 6;
            int s = __ldg(&start_cols[b]);
            int inv = (c < s) ? c : ((c < s + SW) ? (NVIS + c - s) : (c - SW));
            __stcs(&out[VIS_ELEMS + 65536 + m], (float)(r * NCOLS + inv));
        }
    } else if (blk == 0 && tid < 192) {
        // stripe_bounds: 128 elems, row 0 = start, row 1 = start + SW
        unsigned m = tid - 64;
        int b = m & 63;
        int s = __ldg(&start_cols[b]);
        __stcs(&out[VIS_ELEMS + 131072 + m], (float)((m < 64) ? s : s + SW));
    }

    // ---- gather: one warp per output row; 6 front-batched LDG.128 ----
    unsigned warp = blk * 8 + (tid >> 5);
    int lane = tid & 31;
    int b = warp & 63;
    int t = warp >> 6;                         // t in [0,256)
    int j = t & 63;
    int r = t >> 6;
    int s = __ldg(&start_cols[b]);
    int src_t = r * NCOLS + perm_of(j, s);

    const float4* src = patches + ((long)src_t * BATCH + b) * ROW_F4 + lane;
    float4*       dst = (float4*)out + (long)warp * ROW_F4 + lane;

    float4 v0 = src[0];
    float4 v1 = src[32];
    float4 v2 = src[64];
    float4 v3 = src[96];
    float4 v4 = src[128];
    float4 v5 = src[160];
    // streaming stores: evict-first so the input stays L2-resident across replays
    __stcs(&dst[0],   v0);
    __stcs(&dst[32],  v1);
    __stcs(&dst[64],  v2);
    __stcs(&dst[96],  v3);
    __stcs(&dst[128], v4);
    __stcs(&dst[160], v5);
}

extern "C" void kernel_launch(void* const* d_in, const int* in_sizes, int n_in,
                              void* d_out, int out_size) {
    const float4* patches    = (const float4*)d_in[0];
    const int*    start_cols = (const int*)d_in[1];
    float*        out        = (float*)d_out;

    patch_shuffle_fused<<<NBLOCKS, 256>>>(patches, start_cols, out);
}